// round 5
// baseline (speedup 1.0000x reference)
#include <cuda_runtime.h>
#include <cuda_bf16.h>
#include <cuda_fp16.h>
#include <cstdint>

// ---------------- problem constants ----------------
#define B_SZ 512
#define D_SZ 256
#define C_SZ 100000
#define C_PAD 100096              // 782 * 128
#define NCHB 782                  // class chunks of 128
#define MARGIN 0.2f
#define SCALE  30.0f
#define SHIFT  30.0f              // fixed LSE shift
#define WCONV_BLOCKS 12500        // 8 classes per block

// GEMM smem: 4 stages x (A 8KB + B 8KB) = 64KB, + 2KB reduce buffer
#define STAGE_BYTES 16384
#define RBUF_OFF    65536
#define GEMM_SMEM   (65536 + 2048)

// ---------------- device scratch (no runtime alloc) ----------------
__device__ __align__(16) uint8_t g_wq[(size_t)C_PAD * D_SZ];  // l2norm(W) fp8 e4m3; pad rows zero
__device__ __align__(16) uint8_t g_xq[B_SZ * D_SZ];           // fp8(S * l2norm(x))
__device__ __align__(16) float   g_xsn[B_SZ * D_SZ];          // S * l2norm(x) fp32 (accurate)
__device__ float g_winv[C_SZ];                                // 1/max(||w_c||,eps)
__device__ float g_psum[(size_t)B_SZ * NCHB];                 // per-(row,chunk) sum exp(v-SHIFT)
__device__ float g_loss[B_SZ];
__device__ unsigned g_cnt;

// ---------------- PTX helpers ----------------
__device__ __forceinline__ uint32_t smem_u32(const void* p) {
    uint32_t a;
    asm("{ .reg .u64 t; cvta.to.shared.u64 t, %1; cvt.u32.u64 %0, t; }" : "=r"(a) : "l"(p));
    return a;
}
#define CP_ASYNC16(dst, src) \
    asm volatile("cp.async.cg.shared.global [%0], [%1], 16;" :: "r"(dst), "l"(src) : "memory")
#define CP_COMMIT() asm volatile("cp.async.commit_group;" ::: "memory")
#define CP_WAIT(n)  asm volatile("cp.async.wait_group %0;" :: "n"(n) : "memory")

#define LDSM_X4(r0, r1, r2, r3, addr) \
    asm volatile("ldmatrix.sync.aligned.m8n8.x4.shared.b16 {%0,%1,%2,%3}, [%4];" \
        : "=r"(r0), "=r"(r1), "=r"(r2), "=r"(r3) : "r"(addr))

#define MMA_FP8(d0, d1, d2, d3, a0, a1, a2, a3, b0, b1) \
    asm volatile("mma.sync.aligned.m16n8k32.row.col.f32.e4m3.e4m3.f32 " \
        "{%0,%1,%2,%3}, {%4,%5,%6,%7}, {%8,%9}, {%0,%1,%2,%3};" \
        : "+f"(d0), "+f"(d1), "+f"(d2), "+f"(d3) \
        : "r"(a0), "r"(a1), "r"(a2), "r"(a3), "r"(b0), "r"(b1))

// pack 4 fp32 -> 4 fp8 e4m3 bytes (e0 lowest byte)
__device__ __forceinline__ uint32_t pack4_e4m3(float e0, float e1, float e2, float e3) {
    uint16_t p01, p23; uint32_t r;
    asm("cvt.rn.satfinite.e4m3x2.f32 %0, %1, %2;" : "=h"(p01) : "f"(e1), "f"(e0));
    asm("cvt.rn.satfinite.e4m3x2.f32 %0, %1, %2;" : "=h"(p23) : "f"(e3), "f"(e2));
    asm("mov.b32 %0, {%1, %2};" : "=r"(r) : "h"(p01), "h"(p23));
    return r;
}
// dequant 2 fp8 (in a b16) -> float2
__device__ __forceinline__ float2 dequant2(uint16_t v) {
    uint32_t h2;
    asm("cvt.rn.f16x2.e4m3x2 %0, %1;" : "=r"(h2) : "h"(v));
    return __half22float2(*reinterpret_cast<__half2*>(&h2));
}
__device__ __forceinline__ float dot8_fp8(uint32_t xa, uint32_t xb, uint32_t wa, uint32_t wb) {
    uint16_t x0, x1, x2, x3, w0, w1, w2, w3;
    asm("mov.b32 {%0,%1}, %2;" : "=h"(x0), "=h"(x1) : "r"(xa));
    asm("mov.b32 {%0,%1}, %2;" : "=h"(x2), "=h"(x3) : "r"(xb));
    asm("mov.b32 {%0,%1}, %2;" : "=h"(w0), "=h"(w1) : "r"(wa));
    asm("mov.b32 {%0,%1}, %2;" : "=h"(w2), "=h"(w3) : "r"(wb));
    float s = 0.f;
    float2 a, b;
    a = dequant2(x0); b = dequant2(w0); s += a.x * b.x + a.y * b.y;
    a = dequant2(x1); b = dequant2(w1); s += a.x * b.x + a.y * b.y;
    a = dequant2(x2); b = dequant2(w2); s += a.x * b.x + a.y * b.y;
    a = dequant2(x3); b = dequant2(w3); s += a.x * b.x + a.y * b.y;
    return s;
}

// ---------------- kernel 1: fused prep ----------------
// blocks [0, 12500): W rows -> l2norm fp8 (8 classes/block, warp per class) + inv norms
// blocks [12500, 13012): x row -> S*l2norm(x): fp32 + fp8
__global__ void prep_kernel(const float* __restrict__ w, const float* __restrict__ x) {
    if (blockIdx.x < WCONV_BLOCKS) {
        int cls = blockIdx.x * 8 + (threadIdx.x >> 5);
        int lane = threadIdx.x & 31;
        if (cls >= C_SZ) return;
        const float4* wr = (const float4*)(w + (size_t)cls * D_SZ);
        float4 a = wr[lane];
        float4 b = wr[lane + 32];
        float s = a.x*a.x + a.y*a.y + a.z*a.z + a.w*a.w
                + b.x*b.x + b.y*b.y + b.z*b.z + b.w*b.w;
        #pragma unroll
        for (int m = 16; m; m >>= 1) s += __shfl_xor_sync(0xffffffffu, s, m);
        float inv = 1.0f / fmaxf(sqrtf(s), 1e-12f);
        if (lane == 0) g_winv[cls] = inv;
        uint8_t* row = g_wq + (size_t)cls * D_SZ;
        *(uint32_t*)(row + 4 * lane) =
            pack4_e4m3(a.x * inv, a.y * inv, a.z * inv, a.w * inv);
        *(uint32_t*)(row + 128 + 4 * lane) =
            pack4_e4m3(b.x * inv, b.y * inv, b.z * inv, b.w * inv);
    } else {
        int b = blockIdx.x - WCONV_BLOCKS, t = threadIdx.x;   // 256 threads
        if (b == 0 && t == 0) g_cnt = 0;                      // reset completion counter
        float v = x[b * D_SZ + t];
        float s = v * v;
        #pragma unroll
        for (int m = 16; m; m >>= 1) s += __shfl_xor_sync(0xffffffffu, s, m);
        __shared__ float ws[8];
        if ((t & 31) == 0) ws[t >> 5] = s;
        __syncthreads();
        __shared__ float inv;
        __shared__ float xs[256];
        if (t == 0) {
            float tot = 0.f;
            #pragma unroll
            for (int i = 0; i < 8; i++) tot += ws[i];
            inv = 1.0f / fmaxf(sqrtf(tot), 1e-12f);
        }
        __syncthreads();
        float sv = SCALE * v * inv;
        g_xsn[b * D_SZ + t] = sv;
        xs[t] = sv;
        __syncthreads();
        if (t < 64)
            *(uint32_t*)(g_xq + b * D_SZ + 4 * t) =
                pack4_e4m3(xs[4*t], xs[4*t+1], xs[4*t+2], xs[4*t+3]);
    }
}

// ---------------- kernel 2: FP8 MMA GEMM + exp-sum epilogue ----------------
// grid (4, 782). 256 threads = 8 warps (2m x 4n), warp tile 64m x 32n, k32 steps.
// Stage = 64 fp8 of K per row (64 B) -> byte-identical layout to the bf16 version.
__global__ void __launch_bounds__(256, 2)
gemm_lse_kernel() {
    extern __shared__ __align__(1024) char smem[];
    const uint32_t sb = smem_u32(smem);
    const int tid = threadIdx.x, lane = tid & 31, wid = tid >> 5;
    const int wm = wid >> 2, wn = wid & 3;
    const int chunk = blockIdx.y, c0 = chunk * 128, b0 = blockIdx.x * 128;

    // ---- cp.async producer indexing (swizzled 16B chunks; 64 B rows) ----
    const int ldRow = tid >> 2, ldC16 = tid & 3;
    const uint32_t swzOff = (uint32_t)ldRow * 64 +
                            ((uint32_t)(ldC16 ^ ((ldRow >> 1) & 3)) << 4);
    const uint8_t* gA = g_xq + (size_t)(b0 + ldRow) * D_SZ + ldC16 * 16;
    const uint8_t* gB = g_wq + (size_t)(c0 + ldRow) * D_SZ + ldC16 * 16;

    auto load_stage = [&](int kt) {
        uint32_t abase = sb + (kt & 3) * STAGE_BYTES;
        uint32_t bbase = abase + 8192;
        const uint8_t* a = gA + kt * 64;
        const uint8_t* b = gB + kt * 64;
        CP_ASYNC16(abase + swzOff,        a);
        CP_ASYNC16(abase + swzOff + 4096, a + (size_t)64 * D_SZ);
        CP_ASYNC16(bbase + swzOff,        b);
        CP_ASYNC16(bbase + swzOff + 4096, b + (size_t)64 * D_SZ);
        CP_COMMIT();
    };

    // ---- ldmatrix consumer indexing (byte-identical to bf16 k16 case) ----
    const int rA = wm * 64 + (lane & 15);
    const uint32_t aoff = (uint32_t)rA * 64;
    const int saN = (rA >> 1) & 3;
    const int cA = lane >> 4;
    const int rB = wn * 32 + ((lane >> 4) << 3) + (lane & 7);
    const uint32_t boff = (uint32_t)rB * 64;
    const int sbN = (rB >> 1) & 3;
    const int cB = (lane >> 3) & 1;

    float acc[4][4][4];
    #pragma unroll
    for (int i = 0; i < 4; i++)
        #pragma unroll
        for (int j = 0; j < 4; j++)
            #pragma unroll
            for (int e = 0; e < 4; e++) acc[i][j][e] = 0.f;

    auto compute_stage = [&](int st) {
        uint32_t aBase = sb + st * STAGE_BYTES;
        uint32_t bBase = aBase + 8192;
        #pragma unroll
        for (int s = 0; s < 2; s++) {                 // two k32 steps per stage
            uint32_t a_[4][4], b_[2][4];
            #pragma unroll
            for (int mt = 0; mt < 4; mt++) {
                uint32_t ad = aBase + aoff + mt * 1024 +
                              ((uint32_t)((s * 2 + cA) ^ saN) << 4);
                LDSM_X4(a_[mt][0], a_[mt][1], a_[mt][2], a_[mt][3], ad);
            }
            #pragma unroll
            for (int jp = 0; jp < 2; jp++) {
                uint32_t bd = bBase + boff + jp * 1024 +
                              ((uint32_t)((s * 2 + cB) ^ sbN) << 4);
                LDSM_X4(b_[jp][0], b_[jp][1], b_[jp][2], b_[jp][3], bd);
            }
            #pragma unroll
            for (int mt = 0; mt < 4; mt++)
                #pragma unroll
                for (int nt = 0; nt < 4; nt++) {
                    int jp = nt >> 1, hb = (nt & 1) * 2;
                    MMA_FP8(acc[mt][nt][0], acc[mt][nt][1], acc[mt][nt][2], acc[mt][nt][3],
                            a_[mt][0], a_[mt][1], a_[mt][2], a_[mt][3],
                            b_[jp][hb], b_[jp][hb + 1]);
                }
        }
    };

    // ---- pipeline: 4 K-stages, 4 buffers ----
    load_stage(0); load_stage(1); load_stage(2);
    CP_WAIT(2); __syncthreads(); compute_stage(0); load_stage(3);
    CP_WAIT(2); __syncthreads(); compute_stage(1);
    CP_WAIT(1); __syncthreads(); compute_stage(2);
    CP_WAIT(0); __syncthreads(); compute_stage(3);

    // ---- epilogue: per-row sum of exp(v - SHIFT) ----
    const bool edge = (c0 + 128 > C_SZ);
    float es[4][2];
    #pragma unroll
    for (int mt = 0; mt < 4; mt++) { es[mt][0] = 0.f; es[mt][1] = 0.f; }
    #pragma unroll
    for (int mt = 0; mt < 4; mt++)
        #pragma unroll
        for (int nt = 0; nt < 4; nt++) {
            int cgb = c0 + wn * 32 + nt * 8 + (lane & 3) * 2;
            #pragma unroll
            for (int h = 0; h < 2; h++)
                #pragma unroll
                for (int e = 0; e < 2; e++) {
                    float t = __expf(acc[mt][nt][h * 2 + e] - SHIFT);
                    if (edge && (cgb + e >= C_SZ)) t = 0.f;
                    es[mt][h] += t;
                }
        }
    #pragma unroll
    for (int m = 1; m <= 2; m <<= 1)
        #pragma unroll
        for (int mt = 0; mt < 4; mt++) {
            es[mt][0] += __shfl_xor_sync(0xffffffffu, es[mt][0], m);
            es[mt][1] += __shfl_xor_sync(0xffffffffu, es[mt][1], m);
        }

    float* rbuf = (float*)(smem + RBUF_OFF);
    if ((lane & 3) == 0) {
        int rl = lane >> 2;
        #pragma unroll
        for (int mt = 0; mt < 4; mt++) {
            rbuf[(wm * 4 + wn) * 64 + mt * 16 + rl]     = es[mt][0];
            rbuf[(wm * 4 + wn) * 64 + mt * 16 + 8 + rl] = es[mt][1];
        }
    }
    __syncthreads();
    if (tid < 128) {
        int wmx = tid >> 6, rl = tid & 63;
        float s = rbuf[(wmx * 4 + 0) * 64 + rl] + rbuf[(wmx * 4 + 1) * 64 + rl]
                + rbuf[(wmx * 4 + 2) * 64 + rl] + rbuf[(wmx * 4 + 3) * 64 + rl];
        g_psum[(size_t)(b0 + tid) * NCHB + chunk] = s;
    }
}

// ---------------- kernel 3: specials (fp32 accurate + fp8 emulated) + LSE + loss + final ----------------
__global__ void row_kernel(const float* __restrict__ w, const float* __restrict__ lamp,
                           const int* __restrict__ t1, const int* __restrict__ p1,
                           const int* __restrict__ t2, const int* __restrict__ p2,
                           float* __restrict__ out) {
    int b = blockIdx.x;
    int tid = threadIdx.x, wid = tid >> 5, lane = tid & 31;

    __shared__ float sv[4], svraw[4];
    __shared__ int   sidx[4];
    __shared__ float ss[256];
    __shared__ bool  last;

    int i0 = t1[b], i1 = p1[b], i2 = t2[b], i3 = p2[b];

    if (wid < 4) {
        int qi = (wid == 0) ? i0 : (wid == 1) ? i1 : (wid == 2) ? i2 : i3;
        // accurate fp32: S * dot(xn, wn)
        const float4* xa = (const float4*)(g_xsn + (size_t)b * D_SZ);
        const float4* wa = (const float4*)(w + (size_t)qi * D_SZ);
        float winv = g_winv[qi];
        float4 x0 = xa[2*lane], x1 = xa[2*lane+1];
        float4 w0 = wa[2*lane], w1 = wa[2*lane+1];
        float acc = (x0.x*w0.x + x0.y*w0.y + x0.z*w0.z + x0.w*w0.w
                   + x1.x*w1.x + x1.y*w1.y + x1.z*w1.z + x1.w*w1.w) * winv;
        // emulated fp8: same bytes the GEMM consumed
        uint2 xq = *(const uint2*)(g_xq + (size_t)b * D_SZ + lane * 8);
        uint2 wq = *(const uint2*)(g_wq + (size_t)qi * D_SZ + lane * 8);
        float eml = dot8_fp8(xq.x, xq.y, wq.x, wq.y);
        #pragma unroll
        for (int m = 16; m; m >>= 1) {
            acc += __shfl_xor_sync(0xffffffffu, acc, m);
            eml += __shfl_xor_sync(0xffffffffu, eml, m);
        }
        if (lane == 0) {
            float val = acc;                             // S*cos (fp32 accurate)
            if (qi == i0) val = acc - SCALE * MARGIN;    // pre-scale scatter
            if (qi == i1) val = acc / SCALE - MARGIN;    // post-scale scatters
            if (qi == i2) val = acc / SCALE - MARGIN;
            if (qi == i3) val = acc / SCALE - MARGIN;    // last write wins
            svraw[wid] = eml;                            // what the GEMM summed
            sv[wid] = val;
            sidx[wid] = qi;
        }
    }

    float s = 0.f;
    for (int i = tid; i < NCHB; i += 256) s += g_psum[(size_t)b * NCHB + i];
    ss[tid] = s;
    __syncthreads();
    for (int st = 128; st; st >>= 1) {
        if (tid < st) ss[tid] += ss[tid + st];
        __syncthreads();
    }

    if (tid == 0) {
        float S0 = ss[0];
        #pragma unroll
        for (int q = 0; q < 3; q++) {
            bool lastq = true;
            #pragma unroll
            for (int r = q + 1; r < 4; r++) if (sidx[r] == sidx[q]) lastq = false;
            if (lastq) S0 += __expf(sv[q] - SHIFT) - __expf(svraw[q] - SHIFT);
        }
        S0 += __expf(sv[3] - SHIFT) - __expf(svraw[3] - SHIFT);
        float lz = SHIFT + logf(S0);
        float lam = *lamp;
        g_loss[b] = lam * (0.2f * (lz - sv[0]) + 0.8f * (lz - sv[1]))
                  + (1.f - lam) * (0.2f * (lz - sv[2]) + 0.8f * (lz - sv[3]));
        __threadfence();
        last = (atomicAdd(&g_cnt, 1u) == B_SZ - 1);
    }
    __syncthreads();

    if (last) {   // deterministic final reduction by the last-arriving block
        float r = 0.f;
        for (int i = tid; i < B_SZ; i += 256) r += __ldcg(&g_loss[i]);
        ss[tid] = r;
        __syncthreads();
        for (int st = 128; st; st >>= 1) {
            if (tid < st) ss[tid] += ss[tid + st];
            __syncthreads();
        }
        if (tid == 0) out[0] = ss[0] / (float)B_SZ;
    }
}

// ---------------- host launch ----------------
extern "C" void kernel_launch(void* const* d_in, const int* in_sizes, int n_in,
                              void* d_out, int out_size) {
    const float* x   = (const float*)d_in[0];
    const float* w   = (const float*)d_in[1];
    const float* lam = (const float*)d_in[2];
    const int* t1    = (const int*)d_in[3];
    const int* p1    = (const int*)d_in[4];
    const int* t2    = (const int*)d_in[5];
    const int* p2    = (const int*)d_in[6];
    float* out = (float*)d_out;

    static bool attr_set = false;
    if (!attr_set) {
        cudaFuncSetAttribute(gemm_lse_kernel,
                             cudaFuncAttributeMaxDynamicSharedMemorySize, GEMM_SMEM);
        attr_set = true;
    }

    prep_kernel<<<WCONV_BLOCKS + B_SZ, 256>>>(w, x);
    gemm_lse_kernel<<<dim3(4, NCHB), 256, GEMM_SMEM>>>();
    row_kernel<<<B_SZ, 256>>>(w, lam, t1, p1, t2, p2, out);
}